// round 5
// baseline (speedup 1.0000x reference)
#include <cuda_runtime.h>

#define NN   4
#define C    256
#define H    64
#define W    64
#define P    (H*W)
#define CCH  64
#define K2   25
#define HO   128
#define WO   128
#define ENC  100

typedef unsigned long long u64;

__device__ __forceinline__ u64 pack2(float lo, float hi) {
    u64 r; asm("mov.b64 %0, {%1,%2};" : "=l"(r) : "f"(lo), "f"(hi)); return r;
}
__device__ __forceinline__ u64 dup2(float v) {
    u64 r; asm("mov.b64 %0, {%1,%1};" : "=l"(r) : "f"(v)); return r;
}
__device__ __forceinline__ void unpack2(u64 v, float& lo, float& hi) {
    asm("mov.b64 {%0,%1}, %2;" : "=f"(lo), "=f"(hi) : "l"(v));
}
__device__ __forceinline__ u64 fma2(u64 a, u64 b, u64 c) {
    u64 d; asm("fma.rn.f32x2 %0, %1, %2, %3;" : "=l"(d) : "l"(a), "l"(b), "l"(c)); return d;
}
__device__ __forceinline__ u64 add2(u64 a, u64 b) {
    u64 d; asm("add.rn.f32x2 %0, %1, %2;" : "=l"(d) : "l"(a), "l"(b)); return d;
}

// scratch (device globals; no allocations allowed)
__device__ float g_comp[NN*CCH*P];   // 4 MB
__device__ float g_m[NN*ENC*P];      // 6.5 MB  (K-half 0)
__device__ float g_m2[NN*ENC*P];     // 6.5 MB  (K-half 1)
__device__ float g_wt[C*CCH];        // transposed compressor weights

// ---------------------------------------------------------------------------
// Kernel T: transpose Wc (64,256) -> g_wt (256,64)
// ---------------------------------------------------------------------------
__global__ void k_transpose(const float* __restrict__ Wc) {
    int idx = blockIdx.x * 256 + threadIdx.x;
    int oc = idx & 63, c = idx >> 6;
    g_wt[c*CCH + oc] = Wc[oc*C + c];
}

// ---------------------------------------------------------------------------
// Kernel A: 1x1 conv compressor, 64oc x 32px tiles, packed f32x2 over px.
// ---------------------------------------------------------------------------
__global__ __launch_bounds__(128)
void k_compress(const float* __restrict__ x, const float* __restrict__ bc) {
    __shared__ __align__(16) float Ws[16][64];
    __shared__ __align__(16) float Xs[16][32];
    const int n  = blockIdx.y;
    const int p0 = blockIdx.x * 32;
    const int tx = threadIdx.x & 7;    // px group (4 px = 2 pairs)
    const int ty = threadIdx.x >> 3;   // oc group (4 oc)

    u64 acc[4][2];
#pragma unroll
    for (int i = 0; i < 4; i++) { acc[i][0] = 0ull; acc[i][1] = 0ull; }

    for (int c0 = 0; c0 < C; c0 += 16) {
        __syncthreads();
        for (int i = threadIdx.x; i < 1024; i += 128) {
            int k = i >> 6, oc = i & 63;
            Ws[k][oc] = g_wt[(c0 + k)*CCH + oc];
        }
        for (int i = threadIdx.x; i < 512; i += 128) {
            int k = i >> 5, px = i & 31;
            Xs[k][px] = x[(n*C + c0 + k)*P + p0 + px];
        }
        __syncthreads();
#pragma unroll
        for (int k = 0; k < 16; k++) {
            float4 a = *(const float4*)&Ws[k][ty*4];
            u64 b01 = *(const u64*)&Xs[k][tx*4];
            u64 b23 = *(const u64*)&Xs[k][tx*4 + 2];
            float av[4] = {a.x, a.y, a.z, a.w};
#pragma unroll
            for (int i = 0; i < 4; i++) {
                u64 d = dup2(av[i]);
                acc[i][0] = fma2(d, b01, acc[i][0]);
                acc[i][1] = fma2(d, b23, acc[i][1]);
            }
        }
    }
#pragma unroll
    for (int i = 0; i < 4; i++) {
        int oc = ty*4 + i;
        u64 bd = dup2(bc[oc]);
        float* p = &g_comp[(n*CCH + oc)*P + p0 + tx*4];
        *(u64*)p       = add2(acc[i][0], bd);
        *(u64*)(p + 2) = add2(acc[i][1], bd);
    }
}

// ---------------------------------------------------------------------------
// Kernel B: 3x3 conv encoder, packed f32x2 over oc-pairs.
// block = 64 threads: thread = (xg 0..7 -> 2 px, ty 0..7). Tile 8h x 16w.
// 25 oc as 13 float2 pairs (last padded). K split across grid (kh): 32 ch each.
// grid: (32 tiles, 4 n, 4 ocg * 2 kh) = 1024 blocks.
// ---------------------------------------------------------------------------
__global__ __launch_bounds__(64)
void k_encode(const float* __restrict__ We, const float* __restrict__ be) {
    __shared__ __align__(16) float tile[8*184];      // [c][10][18] stride 184
    __shared__ __align__(16) float2 wgt2[8*9*14];    // [c][tap][14 oc-pairs]
    const int bx = blockIdx.x;
    const int h0 = (bx >> 2) * 8;
    const int w0 = (bx & 3) * 16;
    const int n  = blockIdx.y;
    const int oc0 = (blockIdx.z & 3) * 25;
    const int kh  = blockIdx.z >> 2;
    const int cbase = kh * 32;
    const int xg = threadIdx.x & 7;
    const int ty = threadIdx.x >> 3;
    float* __restrict__ gout = kh ? g_m2 : g_m;

    u64 accA[13], accB[13];
#pragma unroll
    for (int q = 0; q < 13; q++) { accA[q] = 0ull; accB[q] = 0ull; }

    for (int cc0 = 0; cc0 < 32; cc0 += 8) {
        const int cs = cbase + cc0;
        __syncthreads();
        for (int idx = threadIdx.x; idx < 8*180; idx += 64) {
            int c = idx / 180, q = idx % 180;
            int yy = q / 18, xx = q % 18;
            int gy = h0 + yy - 1, gx = w0 + xx - 1;
            float v = 0.f;
            if (gy >= 0 && gy < H && gx >= 0 && gx < W)
                v = g_comp[(n*CCH + cs + c)*P + gy*W + gx];
            tile[c*184 + q] = v;
        }
        for (int idx = threadIdx.x; idx < 8*117; idx += 64) {
            int c = idx / 117, r = idx % 117;
            int tap = r / 13, qq = r % 13;
            float wa = We[((oc0 + 2*qq)*CCH + cs + c)*9 + tap];
            float wb = (2*qq + 1 < 25) ? We[((oc0 + 2*qq + 1)*CCH + cs + c)*9 + tap] : 0.f;
            wgt2[(c*9 + tap)*14 + qq] = make_float2(wa, wb);
        }
        __syncthreads();
#pragma unroll 1
        for (int c = 0; c < 8; c++) {
            const int base = c*184 + ty*18 + xg*2;
#pragma unroll
            for (int ky = 0; ky < 3; ky++) {
                float2 fa = *(const float2*)&tile[base + ky*18];
                float2 fb = *(const float2*)&tile[base + ky*18 + 2];
                u64 dv[4];
                dv[0] = dup2(fa.x); dv[1] = dup2(fa.y);
                dv[2] = dup2(fb.x); dv[3] = dup2(fb.y);
#pragma unroll
                for (int kx = 0; kx < 3; kx++) {
                    u64 v0 = dv[kx];        // px0 tap value
                    u64 v1 = dv[kx + 1];    // px1 tap value
                    const float2* wp = &wgt2[(c*9 + ky*3 + kx)*14];
#pragma unroll
                    for (int q2 = 0; q2 < 6; q2++) {
                        ulonglong2 ww = *(const ulonglong2*)(wp + q2*2);
                        accA[q2*2]   = fma2(v0, ww.x, accA[q2*2]);
                        accB[q2*2]   = fma2(v1, ww.x, accB[q2*2]);
                        accA[q2*2+1] = fma2(v0, ww.y, accA[q2*2+1]);
                        accB[q2*2+1] = fma2(v1, ww.y, accB[q2*2+1]);
                    }
                    u64 w12 = *(const u64*)(wp + 12);
                    accA[12] = fma2(v0, w12, accA[12]);
                    accB[12] = fma2(v1, w12, accB[12]);
                }
            }
        }
    }

    const int y = h0 + ty, xpx = w0 + xg*2;
#pragma unroll
    for (int q = 0; q < 13; q++) {
        float a0, a1, b0, b1;
        unpack2(accA[q], a0, a1);   // px0: oc 2q, 2q+1
        unpack2(accB[q], b0, b1);   // px1
        int oc = oc0 + 2*q;
        float bias0 = kh ? 0.f : be[oc];
        *(float2*)&gout[(n*ENC + oc)*P + y*W + xpx] = make_float2(a0 + bias0, b0 + bias0);
        if (2*q + 1 < 25) {
            float bias1 = kh ? 0.f : be[oc + 1];
            *(float2*)&gout[(n*ENC + oc + 1)*P + y*W + xpx] = make_float2(a1 + bias1, b1 + bias1);
        }
    }
}

// ---------------------------------------------------------------------------
// Kernel D: fused pixel-shuffle softmax + reassembly.
// thread = (p 0..63, i vertical subpixel, cl channel lane 0..1).
// Masks: 25 u64 packed over the TWO horizontal subpixels of row i -> 50 regs,
// no spills. Per tap per channel: 1 LDS.32 (2-way i-broadcast) + dup + fma2.
// grid (64 tiles, 4 n, 4 cgrp) = 1024 blocks x 256 thr.
// ---------------------------------------------------------------------------
__global__ __launch_bounds__(256, 2)
void k_reassemble(const float* __restrict__ x, float* __restrict__ out) {
    __shared__ float ms[ENC*65];
    __shared__ float xs[16*168];
    const int t   = blockIdx.x;
    const int n   = blockIdx.y;
    const int c00 = blockIdx.z * 64;
    const int h0 = (t >> 3) * 8, w0 = (t & 7) * 8;
    const int cl = threadIdx.x & 1;
    const int i  = (threadIdx.x >> 1) & 1;
    const int p  = threadIdx.x >> 2;          // 0..63
    const int h  = p >> 3, w = p & 7;
    const int gh = h0 + h, gw = w0 + w;

    // stage encoder logits (sum of the two K-halves), coalesced
    for (int idx = threadIdx.x; idx < ENC*64; idx += 256) {
        int ch = idx >> 6, pp = idx & 63;
        int src = (n*ENC + ch)*P + (h0 + (pp>>3))*W + w0 + (pp&7);
        ms[ch*65 + pp] = g_m[src] + g_m2[src];
    }
    __syncthreads();

    // softmax over 25 taps: thread -> (pixel tid>>2, sub = tid&3)
    {
        const int s = threadIdx.x & 3;
        float tv[25], mx = -1e30f;
#pragma unroll
        for (int k = 0; k < 25; k++) {
            tv[k] = ms[(k*4 + s)*65 + p];
            mx = fmaxf(mx, tv[k]);
        }
        float sum = 0.f;
#pragma unroll
        for (int k = 0; k < 25; k++) { tv[k] = __expf(tv[k] - mx); sum += tv[k]; }
        float inv = 1.f / sum;
#pragma unroll
        for (int k = 0; k < 25; k++) ms[(k*4 + s)*65 + p] = tv[k]*inv;
    }
    __syncthreads();

    // packed masks for this thread's row: {sub 2i, sub 2i+1}  -> 50 regs
    u64 mk[25];
#pragma unroll
    for (int k = 0; k < 25; k++)
        mk[k] = pack2(ms[(k*4 + 2*i)*65 + p], ms[(k*4 + 2*i + 1)*65 + p]);

    int sp = -1;
    if (threadIdx.x < 144) {
        int yy = threadIdx.x / 12, xx = threadIdx.x % 12;
        int gy = h0 + yy - 2, gx = w0 + xx - 2;
        if (gy >= 0 && gy < H && gx >= 0 && gx < W) sp = gy*W + gx;
    }
    const float* xb = x + (n*C + c00)*P;
    float* ob = out + (size_t)(n*C + c00)*HO*WO + (size_t)(2*gh + i)*WO + 2*gw;

    for (int rr = 0; rr < 4; rr++) {
        __syncthreads();
        if (threadIdx.x < 144) {
            const float* xc = xb + rr*16*P;
#pragma unroll
            for (int c = 0; c < 16; c++)
                xs[c*168 + threadIdx.x] = (sp >= 0) ? xc[c*P + sp] : 0.f;
        }
        __syncthreads();
#pragma unroll 2
        for (int cc = 0; cc < 8; cc++) {
            int c = cl + cc*2;                 // banks 8c+w: conflict-free
            const float* xp = &xs[c*168 + h*12 + w];
            u64 acc = 0ull;
#pragma unroll
            for (int ky = 0; ky < 5; ky++)
#pragma unroll
                for (int kx = 0; kx < 5; kx++)
                    acc = fma2(dup2(xp[ky*12 + kx]), mk[ky*5 + kx], acc);
            *(u64*)(ob + (size_t)(rr*16 + c)*HO*WO) = acc;
        }
    }
}

// ---------------------------------------------------------------------------
extern "C" void kernel_launch(void* const* d_in, const int* in_sizes, int n_in,
                              void* d_out, int out_size) {
    const float* x  = (const float*)d_in[0];
    const float* Wc = (const float*)d_in[1];
    const float* bc = (const float*)d_in[2];
    const float* We = (const float*)d_in[3];
    const float* be = (const float*)d_in[4];
    float* out = (float*)d_out;

    k_transpose <<<64, 256>>>(Wc);
    k_compress  <<<dim3(128, NN), 128>>>(x, bc);
    k_encode    <<<dim3(32, NN, 8), 64>>>(We, be);
    k_reassemble<<<dim3(64, NN, 4), 256>>>(x, out);
}